// round 1
// baseline (speedup 1.0000x reference)
#include <cuda_runtime.h>

// Problem geometry: [B, 9, 5, 5] float32. 225 floats per batch.
constexpr int NB = 128;               // batches per CTA
constexpr int THREADS = 128;
constexpr int BATCH_FLOATS = 225;     // 9*5*5
constexpr int SEG_FLOATS = NB * BATCH_FLOATS;  // 28800
constexpr int SMEM_BYTES = SEG_FLOATS * 4;     // 115200

__device__ __forceinline__ float rcp_fast(float x) {
    float r;
    asm("rcp.approx.f32 %0, %1;" : "=f"(r) : "f"(x));
    return r;
}

// Unpivoted 5x5 LU fully in registers.
__device__ __forceinline__ void lu5(float* a) {
#pragma unroll
    for (int k = 0; k < 4; ++k) {
        const float rinv = rcp_fast(a[k * 5 + k]);
#pragma unroll
        for (int i = k + 1; i < 5; ++i) {
            const float c = a[i * 5 + k] * rinv;
            a[i * 5 + k] = c;
#pragma unroll
            for (int j = k + 1; j < 5; ++j)
                a[i * 5 + j] = fmaf(-c, a[k * 5 + j], a[i * 5 + j]);
        }
    }
}

__device__ __forceinline__ void load_blk(const float* m, int blk, float* a) {
    const float* p = m + blk * 25;
#pragma unroll
    for (int i = 0; i < 25; ++i) a[i] = p[i];
}

__device__ __forceinline__ void store_blk(float* m, int blk, const float* a) {
    float* p = m + blk * 25;
#pragma unroll
    for (int i = 0; i < 25; ++i) p[i] = a[i];
}

extern __shared__ float smem[];

__global__ void __launch_bounds__(THREADS)
lu_batched_kernel(const float* __restrict__ in, float* __restrict__ out, int nbatch) {
    const int tid = threadIdx.x;
    const long long segBase = (long long)blockIdx.x * SEG_FLOATS;
    const int batch0 = blockIdx.x * NB;
    const int nb = min(NB, nbatch - batch0);
    const int segFloats = nb * BATCH_FLOATS;

    // ---- Phase 1: coalesced load (identity memcpy; smem layout == global layout) ----
    {
        const int n4 = segFloats >> 2;
        const float4* __restrict__ g4 = (const float4*)(in + segBase);
        float4* s4 = (float4*)smem;
        for (int i = tid; i < n4; i += THREADS) s4[i] = g4[i];
        for (int i = (n4 << 2) + tid; i < segFloats; i += THREADS)
            smem[i] = in[segBase + i];
    }
    __syncthreads();

    // ---- Phase 2: one thread per batch. Bank-conflict-free (stride 225 == 1 mod 32). ----
    if (tid < nb) {
        float* m = smem + tid * BATCH_FLOATS;
        float a[25];

        // Block 0: LU, keep (1,1)
        load_blk(m, 0, a); lu5(a); store_blk(m, 0, a);
        const float s0 = a[6];

        // Block 1: LU, keep (1,1)
        load_blk(m, 1, a); lu5(a); store_blk(m, 1, a);
        const float s1 = a[6];

        // Block 2: LU, keep (2,2),(2,3),(3,2),(3,3)
        load_blk(m, 2, a); lu5(a); store_blk(m, 2, a);
        const float c22 = a[12], c23 = a[13], c32 = a[17], c33 = a[18];

        // Block 5: LU, keep (1,1)
        load_blk(m, 5, a); lu5(a); store_blk(m, 5, a);
        const float s5 = a[6];

        // Block 6: LU, keep (3,3),(3,4),(4,3),(4,4)
        load_blk(m, 6, a); lu5(a); store_blk(m, 6, a);
        const float d33 = a[18], d34 = a[19], d43 = a[23], d44 = a[24];

        // Block 4: untouched passthrough (already staged in smem).

        // Block 3: fill-in from blocks 1,2 then LU
        load_blk(m, 3, a);
        a[0] = a[0] - s1 - c22;   // (0,0) -= A1[1,1] + A2[2,2]
        a[1] -= c23;              // (0,1)
        a[5] -= c32;              // (1,0)
        a[6] -= c33;              // (1,1)
        lu5(a); store_blk(m, 3, a);
        const float t3 = a[6];

        // Block 7: fill-in from blocks 5,6 then LU
        load_blk(m, 7, a);
        a[0] = a[0] - s5 - d33;
        a[1] -= d34;
        a[5] -= d43;
        a[6] -= d44;
        lu5(a); store_blk(m, 7, a);
        const float t7 = a[6];

        // Block 8: fill-in from blocks 0,3,7 then LU
        load_blk(m, 8, a);
        a[0] = a[0] - s0 - t3 - t7;
        lu5(a); store_blk(m, 8, a);
    }
    __syncthreads();

    // ---- Phase 3: coalesced store ----
    {
        const int n4 = segFloats >> 2;
        const float4* s4 = (const float4*)smem;
        float4* __restrict__ g4 = (float4*)(out + segBase);
        for (int i = tid; i < n4; i += THREADS) g4[i] = s4[i];
        for (int i = (n4 << 2) + tid; i < segFloats; i += THREADS)
            out[segBase + i] = smem[i];
    }
}

extern "C" void kernel_launch(void* const* d_in, const int* in_sizes, int n_in,
                              void* d_out, int out_size) {
    const float* in = (const float*)d_in[0];
    float* out = (float*)d_out;
    const int nbatch = in_sizes[0] / BATCH_FLOATS;
    const int grid = (nbatch + NB - 1) / NB;

    static bool attr_set = false;  // idempotent opt-in to >48KB dynamic smem
    if (!attr_set) {
        cudaFuncSetAttribute(lu_batched_kernel,
                             cudaFuncAttributeMaxDynamicSharedMemorySize, SMEM_BYTES);
        attr_set = true;
    }

    lu_batched_kernel<<<grid, THREADS, SMEM_BYTES>>>(in, out, nbatch);
}

// round 2
// speedup vs baseline: 1.1865x; 1.1865x over previous
#include <cuda_runtime.h>

// Problem geometry: [B, 9, 5, 5] float32. 225 floats per batch.
// One 32-thread CTA owns 32 consecutive batches (28800 floats, 28.8 KB smem).
// Small independent CTAs => ~7 resident per SM, phases self-stagger => DRAM saturates.
constexpr int NB = 32;                // batches per CTA
constexpr int THREADS = 32;
constexpr int BATCH_FLOATS = 225;     // 9*5*5
constexpr int SEG_FLOATS = NB * BATCH_FLOATS;  // 7200
constexpr int SMEM_BYTES = SEG_FLOATS * 4;     // 28800

__device__ __forceinline__ float rcp_fast(float x) {
    float r;
    asm("rcp.approx.f32 %0, %1;" : "=f"(r) : "f"(x));
    return r;
}

// Unpivoted 5x5 LU fully in registers.
__device__ __forceinline__ void lu5(float* a) {
#pragma unroll
    for (int k = 0; k < 4; ++k) {
        const float rinv = rcp_fast(a[k * 5 + k]);
#pragma unroll
        for (int i = k + 1; i < 5; ++i) {
            const float c = a[i * 5 + k] * rinv;
            a[i * 5 + k] = c;
#pragma unroll
            for (int j = k + 1; j < 5; ++j)
                a[i * 5 + j] = fmaf(-c, a[k * 5 + j], a[i * 5 + j]);
        }
    }
}

__device__ __forceinline__ void load_blk(const float* m, int blk, float* a) {
    const float* p = m + blk * 25;
#pragma unroll
    for (int i = 0; i < 25; ++i) a[i] = p[i];
}

__device__ __forceinline__ void store_blk(float* m, int blk, const float* a) {
    float* p = m + blk * 25;
#pragma unroll
    for (int i = 0; i < 25; ++i) p[i] = a[i];
}

extern __shared__ float smem[];

__global__ void __launch_bounds__(THREADS)
lu_batched_kernel(const float* __restrict__ in, float* __restrict__ out, int nbatch) {
    const int tid = threadIdx.x;
    const long long segBase = (long long)blockIdx.x * SEG_FLOATS;
    const int batch0 = blockIdx.x * NB;
    const int nb = min(NB, nbatch - batch0);
    const int segFloats = nb * BATCH_FLOATS;

    // ---- Phase 1: coalesced load (identity memcpy; smem layout == global layout) ----
    {
        const int n4 = segFloats >> 2;
        const float4* __restrict__ g4 = (const float4*)(in + segBase);
        float4* s4 = (float4*)smem;
        for (int i = tid; i < n4; i += THREADS) s4[i] = g4[i];
        for (int i = (n4 << 2) + tid; i < segFloats; i += THREADS)
            smem[i] = in[segBase + i];
    }
    __syncwarp();

    // ---- Phase 2: one thread per batch. Bank-conflict-free (stride 225 == 1 mod 32). ----
    if (tid < nb) {
        float* m = smem + tid * BATCH_FLOATS;
        float a[25];

        // Block 0: LU, keep (1,1)
        load_blk(m, 0, a); lu5(a); store_blk(m, 0, a);
        const float s0 = a[6];

        // Block 1: LU, keep (1,1)
        load_blk(m, 1, a); lu5(a); store_blk(m, 1, a);
        const float s1 = a[6];

        // Block 2: LU, keep (2,2),(2,3),(3,2),(3,3)
        load_blk(m, 2, a); lu5(a); store_blk(m, 2, a);
        const float c22 = a[12], c23 = a[13], c32 = a[17], c33 = a[18];

        // Block 5: LU, keep (1,1)
        load_blk(m, 5, a); lu5(a); store_blk(m, 5, a);
        const float s5 = a[6];

        // Block 6: LU, keep (3,3),(3,4),(4,3),(4,4)
        load_blk(m, 6, a); lu5(a); store_blk(m, 6, a);
        const float d33 = a[18], d34 = a[19], d43 = a[23], d44 = a[24];

        // Block 4: untouched passthrough (already staged in smem).

        // Block 3: fill-in from blocks 1,2 then LU
        load_blk(m, 3, a);
        a[0] = a[0] - s1 - c22;   // (0,0) -= A1[1,1] + A2[2,2]
        a[1] -= c23;              // (0,1)
        a[5] -= c32;              // (1,0)
        a[6] -= c33;              // (1,1)
        lu5(a); store_blk(m, 3, a);
        const float t3 = a[6];

        // Block 7: fill-in from blocks 5,6 then LU
        load_blk(m, 7, a);
        a[0] = a[0] - s5 - d33;
        a[1] -= d34;
        a[5] -= d43;
        a[6] -= d44;
        lu5(a); store_blk(m, 7, a);
        const float t7 = a[6];

        // Block 8: fill-in from blocks 0,3,7 then LU
        load_blk(m, 8, a);
        a[0] = a[0] - s0 - t3 - t7;
        lu5(a); store_blk(m, 8, a);
    }
    __syncwarp();

    // ---- Phase 3: coalesced store ----
    {
        const int n4 = segFloats >> 2;
        const float4* s4 = (const float4*)smem;
        float4* __restrict__ g4 = (float4*)(out + segBase);
        for (int i = tid; i < n4; i += THREADS) g4[i] = s4[i];
        for (int i = (n4 << 2) + tid; i < segFloats; i += THREADS)
            out[segBase + i] = smem[i];
    }
}

extern "C" void kernel_launch(void* const* d_in, const int* in_sizes, int n_in,
                              void* d_out, int out_size) {
    const float* in = (const float*)d_in[0];
    float* out = (float*)d_out;
    const int nbatch = in_sizes[0] / BATCH_FLOATS;
    const int grid = (nbatch + NB - 1) / NB;

    static bool attr_set = false;  // idempotent opt-in (cheap; also fine under graph capture)
    if (!attr_set) {
        cudaFuncSetAttribute(lu_batched_kernel,
                             cudaFuncAttributeMaxDynamicSharedMemorySize, SMEM_BYTES);
        attr_set = true;
    }

    lu_batched_kernel<<<grid, THREADS, SMEM_BYTES>>>(in, out, nbatch);
}